// round 6
// baseline (speedup 1.0000x reference)
#include <cuda_runtime.h>
#include <cuda_bf16.h>
#include <math.h>

#define SIZE   512
#define N_PHOS 256
#define H      10
#define THRESH 0.05f

#define MAX_OH 52        // disk span (<=31) + 2H + 1
#define MAX_TW 73        // MAX_OH + 2H (+1 pad)

#define NBLOCKS  N_PHOS          // 256 blocks, one per phosphene
#define NTHREADS 256
#define PX_PER_BLOCK ((SIZE * SIZE) / NBLOCKS)   // 1024

__device__ int      g_max_bits = 0;   // clamped-image max as float bits (>=0)
__device__ unsigned g_bar_count = 0;  // barrier arrival counter (self-restoring)
__device__ unsigned g_bar_gen   = 0;  // barrier generation (monotonic)

static __device__ __forceinline__ int refl(int i) {
    if (i < 0)        i = -i;
    if (i > SIZE - 1) i = 2 * (SIZE - 1) - i;
    return i;
}

// Sense-reversing software grid barrier. Safe: all NBLOCKS are co-resident
// (see launch bounds / smem analysis). State self-restores each use, so the
// kernel is graph-replay deterministic.
static __device__ __forceinline__ void grid_barrier() {
    __syncthreads();
    if (threadIdx.x == 0) {
        unsigned my_gen = *((volatile unsigned*)&g_bar_gen);
        __threadfence();                       // make this block's writes visible
        unsigned arrived = atomicAdd(&g_bar_count, 1u);
        if (arrived == NBLOCKS - 1) {
            atomicExch(&g_bar_count, 0u);
            __threadfence();
            atomicExch(&g_bar_gen, my_gen + 1u);
        } else {
            while (*((volatile unsigned*)&g_bar_gen) == my_gen) { __nanosleep(64); }
        }
        __threadfence();                       // acquire: see other blocks' writes
    }
    __syncthreads();
}

__global__ __launch_bounds__(NTHREADS, 2) void k_fused(
    const float* __restrict__ phoscoding,
    const float* __restrict__ grid,
    float* __restrict__ img)
{
    const int p   = blockIdx.x;
    const int tid = threadIdx.x;

    __shared__ float w[2 * H + 1];
    __shared__ float s_wsum;
    __shared__ float t[MAX_OH][MAX_TW];

    // ---------------- Phase A: zero image, reset max ----------------
    {
        int base = p * PX_PER_BLOCK + tid * 4;     // exactly one float4 per thread
        *reinterpret_cast<float4*>(img + base) = make_float4(0.f, 0.f, 0.f, 0.f);
        if (p == 0 && tid == 0) g_max_bits = 0;
    }

    // ---- overlap: build blur weights for this block's phosphene ----
    const float bright = phoscoding[p];
    const float x = grid[3 * p + 0];
    const float y = grid[3 * p + 1];
    const float r = grid[3 * p + 2];

    const float sigma = r / 3.0f;
    const float half  = ceilf(2.0f * sigma);
    if (tid < 2 * H + 1) {
        float pos = (float)(tid - H);
        float v   = expf(-0.5f * (pos / sigma) * (pos / sigma));
        w[tid]    = (fabsf(pos) <= half) ? v : 0.0f;
    }
    __syncthreads();
    if (tid == 0) {
        float s = 0.0f;
        #pragma unroll
        for (int k = 0; k < 2 * H + 1; k++) s += w[k];
        s_wsum = s;
    }

    grid_barrier();   // image fully zeroed

    // ---------------- Phase B: phosphene scatter ----------------
    {
        const float cx = x - 1.0f, cy = y - 1.0f;   // 0-based center
        const float r2 = r * r;

        int oy0 = max(0,        (int)floorf(cy - r) - H);
        int oy1 = min(SIZE - 1, (int)ceilf (cy + r) + H);
        int ox0 = max(0,        (int)floorf(cx - r) - H);
        int ox1 = min(SIZE - 1, (int)ceilf (cx + r) + H);

        int cLo = max(0,        ox0 - H);
        int cHi = min(SIZE - 1, ox1 + H);

        int oh = oy1 - oy0 + 1;
        int ow = ox1 - ox0 + 1;
        int tw = cHi - cLo + 1;
        if (oh > MAX_OH) oh = MAX_OH;
        if (tw > MAX_TW) tw = MAX_TW;

        // vertical pass: analytic disk mask -> smem
        for (int idx = tid; idx < oh * tw; idx += NTHREADS) {
            int i   = idx / tw;
            int c   = idx - i * tw;
            int row = oy0 + i;
            int col = cLo + c;
            float dxc = (float)(col + 1) - x;       // coordinate is index+1
            float dx2 = dxc * dxc;
            float acc = 0.0f;
            #pragma unroll
            for (int dy = -H; dy <= H; dy++) {
                int   m   = refl(row + dy);
                float dyc = (float)(m + 1) - y;
                float inside = (dx2 + dyc * dyc <= r2) ? 1.0f : 0.0f;
                acc = fmaf(w[dy + H], inside, acc);
            }
            t[i][c] = acc;
        }
        __syncthreads();

        // horizontal pass + threshold + scatter
        const float wsum  = s_wsum;
        const float scale = bright / (wsum * wsum);
        for (int idx = tid; idx < oh * ow; idx += NTHREADS) {
            int i   = idx / ow;
            int j   = idx - i * ow;
            int col = ox0 + j;
            float acc = 0.0f;
            #pragma unroll
            for (int dx = -H; dx <= H; dx++) {
                int cc = refl(col + dx) - cLo;
                acc = fmaf(w[dx + H], t[i][cc], acc);
            }
            float val = acc * scale;
            if (val >= THRESH) {
                atomicAdd(&img[(oy0 + i) * SIZE + (ox0 + j)], val);
            }
        }
    }

    grid_barrier();   // all scatters complete

    // ---------------- Phase C: reduce max of clamped image (read-only) ----
    {
        int base = p * PX_PER_BLOCK + tid * 4;
        // bypass L1 (atomics from other SMs landed in L2)
        float4 v4 = __ldcg(reinterpret_cast<const float4*>(img + base));
        float v = fmaxf(fmaxf(fminf(v4.x, 1.f), fminf(v4.y, 1.f)),
                        fmaxf(fminf(v4.z, 1.f), fminf(v4.w, 1.f)));
        #pragma unroll
        for (int off = 16; off > 0; off >>= 1)
            v = fmaxf(v, __shfl_xor_sync(0xffffffffu, v, off));
        __shared__ float smax[8];
        int lane = tid & 31, wid = tid >> 5;
        if (lane == 0) smax[wid] = v;
        __syncthreads();
        if (wid == 0) {
            v = (lane < (NTHREADS >> 5)) ? smax[lane] : 0.0f;
            #pragma unroll
            for (int off = 4; off > 0; off >>= 1)
                v = fmaxf(v, __shfl_xor_sync(0xffffffffu, v, off));
            if (lane == 0) atomicMax(&g_max_bits, __float_as_int(v));
        }
    }

    grid_barrier();   // global max final

    // ---------------- Phase D: clamp + normalize, single write pass ------
    {
        float m = __int_as_float(__ldcg(&g_max_bits));
        int base = p * PX_PER_BLOCK + tid * 4;
        float4 v4 = __ldcg(reinterpret_cast<const float4*>(img + base));
        float4 o;
        o.x = fminf(v4.x, 1.f); o.y = fminf(v4.y, 1.f);
        o.z = fminf(v4.z, 1.f); o.w = fminf(v4.w, 1.f);
        if (m > 0.0f) { o.x /= m; o.y /= m; o.z /= m; o.w /= m; }
        *reinterpret_cast<float4*>(img + base) = o;
    }
}

extern "C" void kernel_launch(void* const* d_in, const int* in_sizes, int n_in,
                              void* d_out, int out_size) {
    const float* phos = (const float*)d_in[0];
    const float* grid = (const float*)d_in[1];
    if (n_in >= 2 && in_sizes[0] == 3 * N_PHOS && in_sizes[1] == N_PHOS) {
        const float* tmp = phos; phos = grid; grid = tmp;
    }
    float* img = (float*)d_out;

    k_fused<<<NBLOCKS, NTHREADS>>>(phos, grid, img);
}

// round 7
// speedup vs baseline: 1.0099x; 1.0099x over previous
#include <cuda_runtime.h>
#include <cuda_bf16.h>
#include <math.h>

#define SIZE   512
#define N_PHOS 256
#define H      10
#define THRESH 0.05f

#define MAX_OH 52        // disk span (<=31) + 2H + 1
#define MAX_TW 73        // MAX_OH + 2H (+1 pad)

#define NBLOCKS  N_PHOS          // 256 blocks, one per phosphene
#define NTHREADS 256
#define PX_PER_BLOCK ((SIZE * SIZE) / NBLOCKS)   // 1024

__device__ int      g_max_bits = 0;   // clamped-image max as float bits (>=0)
__device__ unsigned g_bar_count = 0;  // barrier arrival counter (self-restoring)
__device__ unsigned g_bar_gen   = 0;  // barrier generation (monotonic)

static __device__ __forceinline__ int refl(int i) {
    if (i < 0)        i = -i;
    if (i > SIZE - 1) i = 2 * (SIZE - 1) - i;
    return i;
}

// Sense-reversing software grid barrier. Safe: all NBLOCKS are co-resident
// (see launch bounds / smem analysis). State self-restores each use, so the
// kernel is graph-replay deterministic.
static __device__ __forceinline__ void grid_barrier() {
    __syncthreads();
    if (threadIdx.x == 0) {
        unsigned my_gen = *((volatile unsigned*)&g_bar_gen);
        __threadfence();                       // make this block's writes visible
        unsigned arrived = atomicAdd(&g_bar_count, 1u);
        if (arrived == NBLOCKS - 1) {
            atomicExch(&g_bar_count, 0u);
            __threadfence();
            atomicExch(&g_bar_gen, my_gen + 1u);
        } else {
            while (*((volatile unsigned*)&g_bar_gen) == my_gen) { __nanosleep(64); }
        }
        __threadfence();                       // acquire: see other blocks' writes
    }
    __syncthreads();
}

__global__ __launch_bounds__(NTHREADS, 2) void k_fused(
    const float* __restrict__ phoscoding,
    const float* __restrict__ grid,
    float* __restrict__ img)
{
    const int p   = blockIdx.x;
    const int tid = threadIdx.x;

    __shared__ float w[2 * H + 1];
    __shared__ float s_wsum;
    __shared__ float t[MAX_OH][MAX_TW];

    // ---------------- Phase A: zero image, reset max ----------------
    {
        int base = p * PX_PER_BLOCK + tid * 4;     // exactly one float4 per thread
        *reinterpret_cast<float4*>(img + base) = make_float4(0.f, 0.f, 0.f, 0.f);
        if (p == 0 && tid == 0) g_max_bits = 0;
    }

    // ---- overlap: build blur weights for this block's phosphene ----
    const float bright = phoscoding[p];
    const float x = grid[3 * p + 0];
    const float y = grid[3 * p + 1];
    const float r = grid[3 * p + 2];

    const float sigma = r / 3.0f;
    const float half  = ceilf(2.0f * sigma);
    if (tid < 2 * H + 1) {
        float pos = (float)(tid - H);
        float v   = expf(-0.5f * (pos / sigma) * (pos / sigma));
        w[tid]    = (fabsf(pos) <= half) ? v : 0.0f;
    }
    __syncthreads();
    if (tid == 0) {
        float s = 0.0f;
        #pragma unroll
        for (int k = 0; k < 2 * H + 1; k++) s += w[k];
        s_wsum = s;
    }

    grid_barrier();   // image fully zeroed

    // ---------------- Phase B: phosphene scatter ----------------
    {
        const float cx = x - 1.0f, cy = y - 1.0f;   // 0-based center
        const float r2 = r * r;

        int oy0 = max(0,        (int)floorf(cy - r) - H);
        int oy1 = min(SIZE - 1, (int)ceilf (cy + r) + H);
        int ox0 = max(0,        (int)floorf(cx - r) - H);
        int ox1 = min(SIZE - 1, (int)ceilf (cx + r) + H);

        int cLo = max(0,        ox0 - H);
        int cHi = min(SIZE - 1, ox1 + H);

        int oh = oy1 - oy0 + 1;
        int ow = ox1 - ox0 + 1;
        int tw = cHi - cLo + 1;
        if (oh > MAX_OH) oh = MAX_OH;
        if (tw > MAX_TW) tw = MAX_TW;

        // vertical pass: analytic disk mask -> smem
        for (int idx = tid; idx < oh * tw; idx += NTHREADS) {
            int i   = idx / tw;
            int c   = idx - i * tw;
            int row = oy0 + i;
            int col = cLo + c;
            float dxc = (float)(col + 1) - x;       // coordinate is index+1
            float dx2 = dxc * dxc;
            float acc = 0.0f;
            #pragma unroll
            for (int dy = -H; dy <= H; dy++) {
                int   m   = refl(row + dy);
                float dyc = (float)(m + 1) - y;
                float inside = (dx2 + dyc * dyc <= r2) ? 1.0f : 0.0f;
                acc = fmaf(w[dy + H], inside, acc);
            }
            t[i][c] = acc;
        }
        __syncthreads();

        // horizontal pass + threshold + scatter
        const float wsum  = s_wsum;
        const float scale = bright / (wsum * wsum);
        for (int idx = tid; idx < oh * ow; idx += NTHREADS) {
            int i   = idx / ow;
            int j   = idx - i * ow;
            int col = ox0 + j;
            float acc = 0.0f;
            #pragma unroll
            for (int dx = -H; dx <= H; dx++) {
                int cc = refl(col + dx) - cLo;
                acc = fmaf(w[dx + H], t[i][cc], acc);
            }
            float val = acc * scale;
            if (val >= THRESH) {
                atomicAdd(&img[(oy0 + i) * SIZE + (ox0 + j)], val);
            }
        }
    }

    grid_barrier();   // all scatters complete

    // ---------------- Phase C: reduce max of clamped image (read-only) ----
    {
        int base = p * PX_PER_BLOCK + tid * 4;
        // bypass L1 (atomics from other SMs landed in L2)
        float4 v4 = __ldcg(reinterpret_cast<const float4*>(img + base));
        float v = fmaxf(fmaxf(fminf(v4.x, 1.f), fminf(v4.y, 1.f)),
                        fmaxf(fminf(v4.z, 1.f), fminf(v4.w, 1.f)));
        #pragma unroll
        for (int off = 16; off > 0; off >>= 1)
            v = fmaxf(v, __shfl_xor_sync(0xffffffffu, v, off));
        __shared__ float smax[8];
        int lane = tid & 31, wid = tid >> 5;
        if (lane == 0) smax[wid] = v;
        __syncthreads();
        if (wid == 0) {
            v = (lane < (NTHREADS >> 5)) ? smax[lane] : 0.0f;
            #pragma unroll
            for (int off = 4; off > 0; off >>= 1)
                v = fmaxf(v, __shfl_xor_sync(0xffffffffu, v, off));
            if (lane == 0) atomicMax(&g_max_bits, __float_as_int(v));
        }
    }

    grid_barrier();   // global max final

    // ---------------- Phase D: clamp + normalize, single write pass ------
    {
        float m = __int_as_float(__ldcg(&g_max_bits));
        int base = p * PX_PER_BLOCK + tid * 4;
        float4 v4 = __ldcg(reinterpret_cast<const float4*>(img + base));
        float4 o;
        o.x = fminf(v4.x, 1.f); o.y = fminf(v4.y, 1.f);
        o.z = fminf(v4.z, 1.f); o.w = fminf(v4.w, 1.f);
        if (m > 0.0f) { o.x /= m; o.y /= m; o.z /= m; o.w /= m; }
        *reinterpret_cast<float4*>(img + base) = o;
    }
}

extern "C" void kernel_launch(void* const* d_in, const int* in_sizes, int n_in,
                              void* d_out, int out_size) {
    const float* phos = (const float*)d_in[0];
    const float* grid = (const float*)d_in[1];
    if (n_in >= 2 && in_sizes[0] == 3 * N_PHOS && in_sizes[1] == N_PHOS) {
        const float* tmp = phos; phos = grid; grid = tmp;
    }
    float* img = (float*)d_out;

    k_fused<<<NBLOCKS, NTHREADS>>>(phos, grid, img);
}